// round 2
// baseline (speedup 1.0000x reference)
#include <cuda_runtime.h>

#define NV 17
#define NC 64
#define NN 128
#define NB 64
#define NT 256
#define TILE_M 64

#define YS_STRIDE 68
#define SMEM_BYTES ((NC * NN + TILE_M * YS_STRIDE) * 4)

__device__ __align__(16) float g_W[NV * NC * NN];
__device__ __align__(16) float g_bias[NN];

// ---------------------------------------------------------------------------
// Prep: a[v,n] = sum_m softmax_n(mat[m,v] * amask[m,v,n])
//       g_W[v,c,n] = kernel[v,c,n] * a[v,n] * gamma[n]/sqrt(var[n]+eps)
//       g_bias[n]  = beta[n] - mean[n]*scale[n]
// ---------------------------------------------------------------------------
__global__ void prep_kernel(const float* __restrict__ mat,
                            const float* __restrict__ amask,
                            const float* __restrict__ kern,
                            const float* __restrict__ gamma,
                            const float* __restrict__ beta,
                            const float* __restrict__ mean,
                            const float* __restrict__ var)
{
    const int v = blockIdx.x;
    const int n = threadIdx.x;            // 0..127
    const int lane = n & 31, wid = n >> 5;
    __shared__ float red[4];
    float acc = 0.f;

    for (int m = 0; m < NV; ++m) {
        float z = mat[m * NV + v] * amask[(m * NV + v) * NN + n];
        // block max over n
        float mx = z;
        #pragma unroll
        for (int o = 16; o > 0; o >>= 1)
            mx = fmaxf(mx, __shfl_xor_sync(0xffffffffu, mx, o));
        __syncthreads();
        if (lane == 0) red[wid] = mx;
        __syncthreads();
        mx = fmaxf(fmaxf(red[0], red[1]), fmaxf(red[2], red[3]));
        float e = expf(z - mx);
        // block sum over n
        float s = e;
        #pragma unroll
        for (int o = 16; o > 0; o >>= 1)
            s += __shfl_xor_sync(0xffffffffu, s, o);
        __syncthreads();
        if (lane == 0) red[wid] = s;
        __syncthreads();
        s = red[0] + red[1] + red[2] + red[3];
        acc += e / s;
        __syncthreads();
    }

    const float scale = gamma[n] * rsqrtf(var[n] + 1e-3f);
    const float an = acc * scale;
    for (int c = 0; c < NC; ++c) {
        int idx = (v * NC + c) * NN + n;
        g_W[idx] = kern[idx] * an;
    }
    if (v == 0) g_bias[n] = beta[n] - mean[n] * scale;
}

// ---------------------------------------------------------------------------
// Main GEMM: per CTA, 64 bt-rows x N=128 for one v, K=C=64.
// Packed f32x2 FFMA (full-rate fp32) with fused BN+ReLU epilogue.
// ---------------------------------------------------------------------------
__device__ __forceinline__ unsigned long long pack2(float x) {
    unsigned long long r;
    asm("mov.b64 %0, {%1, %1};" : "=l"(r) : "f"(x));
    return r;
}
__device__ __forceinline__ void ffma2(unsigned long long& d,
                                      unsigned long long a,
                                      unsigned long long b) {
    asm("fma.rn.f32x2 %0, %1, %2, %0;" : "+l"(d) : "l"(a), "l"(b));
}

__global__ void __launch_bounds__(256, 2)
gemm_kernel(const float* __restrict__ x, float* __restrict__ out)
{
    extern __shared__ float smem[];
    float* Ws = smem;                    // [NC][NN] 32 KB
    float* Ys = smem + NC * NN;          // [TILE_M][YS_STRIDE] padded

    const int v = blockIdx.y;
    const int tile = blockIdx.x;
    const int tid = threadIdx.x;

    // Load fused weights for this v (L2-resident after wave 1)
    {
        const float4* Wg = (const float4*)(g_W + v * (NC * NN));
        float4* Wd = (float4*)Ws;
        #pragma unroll
        for (int i = 0; i < 8; i++) Wd[tid + 256 * i] = Wg[tid + 256 * i];
    }
    // Load Y tile = inputs[b,0,t,v,:] + inputs[b,1,t,v,:]
    const int r0 = tile * TILE_M;
    for (int i = tid; i < TILE_M * 16; i += 256) {
        int row = i >> 4, c4 = i & 15;
        int r = r0 + row;
        int b = r >> 8, t = r & 255;                 // T = 256
        int base = ((b * 2) * NT + t) * (NV * NC) + v * NC + c4 * 4;
        float4 a0 = *(const float4*)(x + base);
        float4 a1 = *(const float4*)(x + base + NT * NV * NC);
        float4 s;
        s.x = a0.x + a1.x; s.y = a0.y + a1.y;
        s.z = a0.z + a1.z; s.w = a0.w + a1.w;
        *(float4*)(Ys + row * YS_STRIDE + c4 * 4) = s;
    }
    __syncthreads();

    const int tx = tid & 15;             // 16 n-groups: n = tx*2 + j*32 (+0/1)
    const int ty = tid >> 4;             // 16 m-groups: m = ty*4 + i
    unsigned long long acc[4][4];
    #pragma unroll
    for (int i = 0; i < 4; i++)
        #pragma unroll
        for (int j = 0; j < 4; j++) acc[i][j] = 0ull;

    const float* yb = Ys + ty * 4 * YS_STRIDE;
    const float* wb = Ws + tx * 2;

    #pragma unroll 16
    for (int k = 0; k < NC; k++) {
        unsigned long long w[4];
        #pragma unroll
        for (int j = 0; j < 4; j++)
            w[j] = *(const unsigned long long*)(wb + k * NN + j * 32);
        #pragma unroll
        for (int i = 0; i < 4; i++) {
            unsigned long long yd = pack2(yb[i * YS_STRIDE + k]);
            #pragma unroll
            for (int j = 0; j < 4; j++) ffma2(acc[i][j], yd, w[j]);
        }
    }

    // Epilogue: + bias, ReLU, store
    #pragma unroll
    for (int i = 0; i < 4; i++) {
        int row = r0 + ty * 4 + i;
        float* o = out + (row * NV + v) * NN + tx * 2;
        #pragma unroll
        for (int j = 0; j < 4; j++) {
            float lo, hi;
            asm("mov.b64 {%0, %1}, %2;" : "=f"(lo), "=f"(hi) : "l"(acc[i][j]));
            int n = tx * 2 + j * 32;
            float2 r;
            r.x = fmaxf(lo + g_bias[n],     0.f);
            r.y = fmaxf(hi + g_bias[n + 1], 0.f);
            *(float2*)(o + j * 32) = r;
        }
    }
}

extern "C" void kernel_launch(void* const* d_in, const int* in_sizes, int n_in,
                              void* d_out, int out_size)
{
    const float* inputs = (const float*)d_in[0];
    const float* mat    = (const float*)d_in[1];
    const float* amask  = (const float*)d_in[2];
    const float* kern   = (const float*)d_in[3];
    const float* gamma  = (const float*)d_in[4];
    const float* beta   = (const float*)d_in[5];
    const float* mean   = (const float*)d_in[6];
    const float* var    = (const float*)d_in[7];
    float* out = (float*)d_out;

    cudaFuncSetAttribute(gemm_kernel,
                         cudaFuncAttributeMaxDynamicSharedMemorySize,
                         SMEM_BYTES);

    prep_kernel<<<NV, NN>>>(mat, amask, kern, gamma, beta, mean, var);
    gemm_kernel<<<dim3((NB * NT) / TILE_M, NV), 256, SMEM_BYTES>>>(inputs, out);
}

// round 4
// speedup vs baseline: 1.2274x; 1.2274x over previous
#include <cuda_runtime.h>
#include <cuda_bf16.h>
#include <cstdint>

#define NV 17
#define NC 64
#define NN 128
#define NB 64
#define NT 256
#define TILE_M 128

#define KPAD 72                       // 64 bf16 + 8 pad -> 144B rows, LDSM conflict-free
#define ROWB (KPAD * 2)               // 144 bytes per row

// smem byte offsets
#define SM_AH 0
#define SM_AL (SM_AH + TILE_M * ROWB)     // 18432
#define SM_BH (SM_AL + TILE_M * ROWB)
#define SM_BL (SM_BH + NN * ROWB)
#define SM_BIAS (SM_BL + NN * ROWB)       // 73728
#define SMEM_BYTES (SM_BIAS + NN * 4)     // 74240

__device__ __align__(16) unsigned short g_Wh[NV * NN * KPAD];  // [v][n][k] padded
__device__ __align__(16) unsigned short g_Wl[NV * NN * KPAD];
__device__ __align__(16) float g_bias[NN];

__device__ __forceinline__ uint32_t smem_u32(const void* p) {
    uint32_t a;
    asm("{ .reg .u64 t; cvta.to.shared.u64 t, %1; cvt.u32.u64 %0, t; }" : "=r"(a) : "l"(p));
    return a;
}

__device__ __forceinline__ void split_bf16(float x, unsigned short& h, unsigned short& l) {
    __nv_bfloat16 hb = __float2bfloat16(x);
    h = *(unsigned short*)&hb;
    float r = x - __bfloat162float(hb);
    __nv_bfloat16 lb = __float2bfloat16(r);
    l = *(unsigned short*)&lb;
}

__device__ __forceinline__ void ldsm_x4(uint32_t* r, uint32_t addr) {
    asm volatile("ldmatrix.sync.aligned.m8n8.x4.shared.b16 {%0,%1,%2,%3}, [%4];"
        : "=r"(r[0]), "=r"(r[1]), "=r"(r[2]), "=r"(r[3]) : "r"(addr));
}
__device__ __forceinline__ void ldsm_x2(uint32_t* r, uint32_t addr) {
    asm volatile("ldmatrix.sync.aligned.m8n8.x2.shared.b16 {%0,%1}, [%2];"
        : "=r"(r[0]), "=r"(r[1]) : "r"(addr));
}
__device__ __forceinline__ void mma_bf16(float* c, const uint32_t* a, const uint32_t* b) {
    asm volatile(
        "mma.sync.aligned.m16n8k16.row.col.f32.bf16.bf16.f32 "
        "{%0,%1,%2,%3}, {%4,%5,%6,%7}, {%8,%9}, {%0,%1,%2,%3};"
        : "+f"(c[0]), "+f"(c[1]), "+f"(c[2]), "+f"(c[3])
        : "r"(a[0]), "r"(a[1]), "r"(a[2]), "r"(a[3]), "r"(b[0]), "r"(b[1]));
}

// ---------------------------------------------------------------------------
// Prep: a[v,n] = sum_m softmax_n(mat[m,v]*amask[m,v,n]); fold BN scale into W.
// Emit W'[v][n][k] split to bf16 hi/lo, padded rows (ldmatrix-ready).
// ---------------------------------------------------------------------------
__global__ void prep_kernel(const float* __restrict__ mat,
                            const float* __restrict__ amask,
                            const float* __restrict__ kern,
                            const float* __restrict__ gamma,
                            const float* __restrict__ beta,
                            const float* __restrict__ mean,
                            const float* __restrict__ var)
{
    const int v = blockIdx.x;
    const int n = threadIdx.x;            // 0..127
    const int lane = n & 31, wid = n >> 5;
    __shared__ float red[4];
    float acc = 0.f;

    for (int m = 0; m < NV; ++m) {
        float z = mat[m * NV + v] * amask[(m * NV + v) * NN + n];
        float mx = z;
        #pragma unroll
        for (int o = 16; o > 0; o >>= 1)
            mx = fmaxf(mx, __shfl_xor_sync(0xffffffffu, mx, o));
        __syncthreads();
        if (lane == 0) red[wid] = mx;
        __syncthreads();
        mx = fmaxf(fmaxf(red[0], red[1]), fmaxf(red[2], red[3]));
        float e = expf(z - mx);
        float s = e;
        #pragma unroll
        for (int o = 16; o > 0; o >>= 1)
            s += __shfl_xor_sync(0xffffffffu, s, o);
        __syncthreads();
        if (lane == 0) red[wid] = s;
        __syncthreads();
        s = red[0] + red[1] + red[2] + red[3];
        acc += e / s;
        __syncthreads();
    }

    const float scale = gamma[n] * rsqrtf(var[n] + 1e-3f);
    const float an = acc * scale;

    unsigned short* wh = g_Wh + ((size_t)v * NN + n) * KPAD;
    unsigned short* wl = g_Wl + ((size_t)v * NN + n) * KPAD;
    for (int c = 0; c < NC; ++c) {
        float w = kern[(v * NC + c) * NN + n] * an;
        unsigned short h, l;
        split_bf16(w, h, l);
        wh[c] = h; wl[c] = l;
    }
    #pragma unroll
    for (int c = NC; c < KPAD; ++c) { wh[c] = 0; wl[c] = 0; }
    if (v == 0) g_bias[n] = beta[n] - mean[n] * scale;
}

// ---------------------------------------------------------------------------
// GEMM via mma.sync bf16 (3-product fp32 emulation), fused BN+ReLU epilogue.
// CTA: 128 bt-rows x 128 n for one v, K=64. 8 warps, each 32m x 64n.
// ---------------------------------------------------------------------------
__global__ void __launch_bounds__(256, 2)
gemm_kernel(const float* __restrict__ x, float* __restrict__ out)
{
    extern __shared__ __align__(16) char smem[];
    const uint32_t sbase = smem_u32(smem);
    const int tid = threadIdx.x;
    const int wid = tid >> 5;
    const int lane = tid & 31;
    const int v = blockIdx.y;
    const int r0 = blockIdx.x * TILE_M;

    // --- Fill A tiles: y = person0 + person1, split to bf16 hi/lo ---
    {
        const int m = tid >> 1;
        const int k0 = (tid & 1) * 32;
        const int r = r0 + m;
        const int b = r >> 8, t = r & 255;
        const float* p0 = x + (((b * 2 + 0) * NT + t) * NV + v) * NC + k0;
        const float* p1 = p0 + (size_t)NT * NV * NC;
        char* Ah = smem + SM_AH + m * ROWB + k0 * 2;
        char* Al = smem + SM_AL + m * ROWB + k0 * 2;
        #pragma unroll
        for (int i = 0; i < 8; i++) {
            float4 a0 = *(const float4*)(p0 + i * 4);
            float4 a1 = *(const float4*)(p1 + i * 4);
            float y0 = a0.x + a1.x, y1 = a0.y + a1.y;
            float y2 = a0.z + a1.z, y3 = a0.w + a1.w;
            unsigned short h0,l0,h1,l1,h2,l2,h3,l3;
            split_bf16(y0, h0, l0); split_bf16(y1, h1, l1);
            split_bf16(y2, h2, l2); split_bf16(y3, h3, l3);
            uint2 ph, pl;
            ph.x = (uint32_t)h0 | ((uint32_t)h1 << 16);
            ph.y = (uint32_t)h2 | ((uint32_t)h3 << 16);
            pl.x = (uint32_t)l0 | ((uint32_t)l1 << 16);
            pl.y = (uint32_t)l2 | ((uint32_t)l3 << 16);
            *(uint2*)(Ah + i * 8) = ph;
            *(uint2*)(Al + i * 8) = pl;
        }
        // zero K padding (cols 64..71) for rows this thread owns
        if (k0 == 32) {
            *(uint4*)(smem + SM_AH + m * ROWB + 128) = make_uint4(0,0,0,0);
            *(uint4*)(smem + SM_AL + m * ROWB + 128) = make_uint4(0,0,0,0);
        }
    }
    // --- Fill B tiles: straight copy of pre-split, pre-padded weights ---
    {
        const uint4* gh = (const uint4*)(g_Wh + (size_t)v * NN * KPAD);
        const uint4* gl = (const uint4*)(g_Wl + (size_t)v * NN * KPAD);
        uint4* bh = (uint4*)(smem + SM_BH);
        uint4* bl = (uint4*)(smem + SM_BL);
        for (int i = tid; i < NN * ROWB / 16; i += 256) {
            bh[i] = gh[i];
            bl[i] = gl[i];
        }
        if (tid < NN) ((float*)(smem + SM_BIAS))[tid] = g_bias[tid];
    }
    __syncthreads();

    // --- Main MMA loop ---
    const int warp_m = (wid & 3) * 32;     // 4 m-warps
    const int warp_n = (wid >> 2) * 64;    // 2 n-warps

    const uint32_t a_lane = ((lane & 7) + ((lane >> 3) & 1) * 8) * ROWB
                          + ((lane >> 4) & 1) * 16;
    const uint32_t b_lane = (lane & 7) * ROWB + ((lane >> 3) & 1) * 16;

    float acc[2][8][4];
    #pragma unroll
    for (int i = 0; i < 2; i++)
        #pragma unroll
        for (int j = 0; j < 8; j++)
            #pragma unroll
            for (int q = 0; q < 4; q++) acc[i][j][q] = 0.f;

    const uint32_t aBaseH = sbase + SM_AH + warp_m * ROWB + a_lane;
    const uint32_t aBaseL = sbase + SM_AL + warp_m * ROWB + a_lane;
    const uint32_t bBaseH = sbase + SM_BH + warp_n * ROWB + b_lane;
    const uint32_t bBaseL = sbase + SM_BL + warp_n * ROWB + b_lane;

    #pragma unroll
    for (int ks = 0; ks < 4; ks++) {
        uint32_t ah[2][4], al[2][4];
        #pragma unroll
        for (int mb = 0; mb < 2; mb++) {
            ldsm_x4(ah[mb], aBaseH + mb * 16 * ROWB + ks * 32);
            ldsm_x4(al[mb], aBaseL + mb * 16 * ROWB + ks * 32);
        }
        #pragma unroll
        for (int nb = 0; nb < 8; nb++) {
            uint32_t bh[2], bl[2];
            ldsm_x2(bh, bBaseH + nb * 8 * ROWB + ks * 32);
            ldsm_x2(bl, bBaseL + nb * 8 * ROWB + ks * 32);
            #pragma unroll
            for (int mb = 0; mb < 2; mb++) {
                mma_bf16(acc[mb][nb], ah[mb], bh);
                mma_bf16(acc[mb][nb], al[mb], bh);
                mma_bf16(acc[mb][nb], ah[mb], bl);
            }
        }
    }

    // --- Epilogue: bias + ReLU + store ---
    const float* bs = (const float*)(smem + SM_BIAS);
    const int qrow = lane >> 2;
    const int qcol = (lane & 3) * 2;
    #pragma unroll
    for (int mb = 0; mb < 2; mb++) {
        #pragma unroll
        for (int nb = 0; nb < 8; nb++) {
            const int n = warp_n + nb * 8 + qcol;
            const float b0 = bs[n], b1 = bs[n + 1];
            const int mlo = warp_m + mb * 16 + qrow;
            float* o0 = out + ((size_t)(r0 + mlo) * NV + v) * NN + n;
            float* o1 = o0 + (size_t)8 * NV * NN;
            float2 r0v, r1v;
            r0v.x = fmaxf(acc[mb][nb][0] + b0, 0.f);
            r0v.y = fmaxf(acc[mb][nb][1] + b1, 0.f);
            r1v.x = fmaxf(acc[mb][nb][2] + b0, 0.f);
            r1v.y = fmaxf(acc[mb][nb][3] + b1, 0.f);
            *(float2*)o0 = r0v;
            *(float2*)o1 = r1v;
        }
    }
}

extern "C" void kernel_launch(void* const* d_in, const int* in_sizes, int n_in,
                              void* d_out, int out_size)
{
    const float* inputs = (const float*)d_in[0];
    const float* mat    = (const float*)d_in[1];
    const float* amask  = (const float*)d_in[2];
    const float* kern   = (const float*)d_in[3];
    const float* gamma  = (const float*)d_in[4];
    const float* beta   = (const float*)d_in[5];
    const float* mean   = (const float*)d_in[6];
    const float* var    = (const float*)d_in[7];
    float* out = (float*)d_out;

    cudaFuncSetAttribute(gemm_kernel,
                         cudaFuncAttributeMaxDynamicSharedMemorySize,
                         SMEM_BYTES);

    prep_kernel<<<NV, NN>>>(mat, amask, kern, gamma, beta, mean, var);
    gemm_kernel<<<dim3((NB * NT) / TILE_M, NV), 256, SMEM_BYTES>>>(inputs, out);
}

// round 6
// speedup vs baseline: 1.5651x; 1.2752x over previous
#include <cuda_runtime.h>
#include <cuda_bf16.h>
#include <cstdint>

#define NV 17
#define NC 64
#define NN 128
#define NB 64
#define NT 256
#define TILE_M 64

#define KPAD 72                       // 64 bf16 + 8 pad -> 144B rows, LDSM conflict-free
#define ROWB (KPAD * 2)               // 144 bytes per row

// smem byte offsets
#define SM_AH 0
#define SM_AL (SM_AH + TILE_M * ROWB)       // 9216
#define SM_BH (SM_AL + TILE_M * ROWB)       // 18432
#define SM_BL (SM_BH + NN * ROWB)
#define SM_BIAS (SM_BL + NN * ROWB)
#define SMEM_BYTES (SM_BIAS + NN * 4)       // 55808

__device__ __align__(16) unsigned short g_Wh[NV * NN * KPAD];  // [v][n][k] padded
__device__ __align__(16) unsigned short g_Wl[NV * NN * KPAD];
__device__ __align__(16) float g_bias[NN];

__device__ __forceinline__ uint32_t smem_u32(const void* p) {
    uint32_t a;
    asm("{ .reg .u64 t; cvta.to.shared.u64 t, %1; cvt.u32.u64 %0, t; }" : "=r"(a) : "l"(p));
    return a;
}

__device__ __forceinline__ void split_bf16(float x, unsigned short& h, unsigned short& l) {
    __nv_bfloat16 hb = __float2bfloat16(x);
    h = *(unsigned short*)&hb;
    float r = x - __bfloat162float(hb);
    __nv_bfloat16 lb = __float2bfloat16(r);
    l = *(unsigned short*)&lb;
}

__device__ __forceinline__ void ldsm_x4(uint32_t* r, uint32_t addr) {
    asm volatile("ldmatrix.sync.aligned.m8n8.x4.shared.b16 {%0,%1,%2,%3}, [%4];"
        : "=r"(r[0]), "=r"(r[1]), "=r"(r[2]), "=r"(r[3]) : "r"(addr));
}
__device__ __forceinline__ void mma_bf16(float* c, const uint32_t* a, const uint32_t* b) {
    asm volatile(
        "mma.sync.aligned.m16n8k16.row.col.f32.bf16.bf16.f32 "
        "{%0,%1,%2,%3}, {%4,%5,%6,%7}, {%8,%9}, {%0,%1,%2,%3};"
        : "+f"(c[0]), "+f"(c[1]), "+f"(c[2]), "+f"(c[3])
        : "r"(a[0]), "r"(a[1]), "r"(a[2]), "r"(a[3]), "r"(b[0]), "r"(b[1]));
}

// ---------------------------------------------------------------------------
// Prep: grid (NV, 4). Each block: softmax a[v,n] (redundant per c-chunk, cheap),
// then emits W'[v][n][k] bf16 hi/lo for a 16-wide c-chunk, padded rows.
// ---------------------------------------------------------------------------
__global__ void prep_kernel(const float* __restrict__ mat,
                            const float* __restrict__ amask,
                            const float* __restrict__ kern,
                            const float* __restrict__ gamma,
                            const float* __restrict__ beta,
                            const float* __restrict__ mean,
                            const float* __restrict__ var)
{
    const int v = blockIdx.x;
    const int cchunk = blockIdx.y;        // 0..3, covers c = cchunk*16 .. +15
    const int n = threadIdx.x;            // 0..127
    const int lane = n & 31, wid = n >> 5;
    __shared__ float red[4];
    float acc = 0.f;

    for (int m = 0; m < NV; ++m) {
        float z = mat[m * NV + v] * amask[(m * NV + v) * NN + n];
        float mx = z;
        #pragma unroll
        for (int o = 16; o > 0; o >>= 1)
            mx = fmaxf(mx, __shfl_xor_sync(0xffffffffu, mx, o));
        __syncthreads();
        if (lane == 0) red[wid] = mx;
        __syncthreads();
        mx = fmaxf(fmaxf(red[0], red[1]), fmaxf(red[2], red[3]));
        float e = expf(z - mx);
        float s = e;
        #pragma unroll
        for (int o = 16; o > 0; o >>= 1)
            s += __shfl_xor_sync(0xffffffffu, s, o);
        __syncthreads();
        if (lane == 0) red[wid] = s;
        __syncthreads();
        s = red[0] + red[1] + red[2] + red[3];
        acc += e / s;
        __syncthreads();
    }

    const float scale = gamma[n] * rsqrtf(var[n] + 1e-3f);
    const float an = acc * scale;

    unsigned short* wh = g_Wh + ((size_t)v * NN + n) * KPAD + cchunk * 16;
    unsigned short* wl = g_Wl + ((size_t)v * NN + n) * KPAD + cchunk * 16;
    unsigned short hb[16], lb[16];
    #pragma unroll
    for (int i = 0; i < 16; ++i) {
        int c = cchunk * 16 + i;
        float w = kern[(v * NC + c) * NN + n] * an;
        split_bf16(w, hb[i], lb[i]);
    }
    #pragma unroll
    for (int i = 0; i < 16; i += 8) {
        uint4 ph, pl;
        ph.x = hb[i+0] | ((uint32_t)hb[i+1] << 16);
        ph.y = hb[i+2] | ((uint32_t)hb[i+3] << 16);
        ph.z = hb[i+4] | ((uint32_t)hb[i+5] << 16);
        ph.w = hb[i+6] | ((uint32_t)hb[i+7] << 16);
        pl.x = lb[i+0] | ((uint32_t)lb[i+1] << 16);
        pl.y = lb[i+2] | ((uint32_t)lb[i+3] << 16);
        pl.z = lb[i+4] | ((uint32_t)lb[i+5] << 16);
        pl.w = lb[i+6] | ((uint32_t)lb[i+7] << 16);
        *(uint4*)(wh + i) = ph;
        *(uint4*)(wl + i) = pl;
    }
    if (cchunk == 0) {
        // zero the K pad (c = 64..71)
        unsigned short* ph = g_Wh + ((size_t)v * NN + n) * KPAD + NC;
        unsigned short* pl = g_Wl + ((size_t)v * NN + n) * KPAD + NC;
        *(uint4*)ph = make_uint4(0,0,0,0);
        *(uint4*)pl = make_uint4(0,0,0,0);
        if (v == 0) g_bias[n] = beta[n] - mean[n] * scale;
    }
}

// ---------------------------------------------------------------------------
// GEMM via mma.sync bf16 (3-product fp32 emulation), fused BN+ReLU epilogue.
// CTA: 64 bt-rows x 128 n for one v, K=64. 8 warps (2m x 4n), each 32m x 32n.
// ---------------------------------------------------------------------------
__global__ void __launch_bounds__(256, 3)
gemm_kernel(const float* __restrict__ x, float* __restrict__ out)
{
    extern __shared__ __align__(16) char smem[];
    const uint32_t sbase = smem_u32(smem);
    const int tid = threadIdx.x;
    const int wid = tid >> 5;
    const int lane = tid & 31;
    const int v = blockIdx.y;
    const int r0 = blockIdx.x * TILE_M;

    // --- Fill B tiles first (independent LDG stream) ---
    {
        const uint4* gh = (const uint4*)(g_Wh + (size_t)v * NN * KPAD);
        const uint4* gl = (const uint4*)(g_Wl + (size_t)v * NN * KPAD);
        uint4* bh = (uint4*)(smem + SM_BH);
        uint4* bl = (uint4*)(smem + SM_BL);
        #pragma unroll
        for (int i = 0; i < NN * ROWB / 16 / 256; i++) {       // 4 full rounds
            bh[tid + 256 * i] = gh[tid + 256 * i];
            bl[tid + 256 * i] = gl[tid + 256 * i];
        }
        {   // remainder (1152 - 1024 = 128 uint4)
            int i = 1024 + tid;
            if (tid < 128) { bh[i] = gh[i]; bl[i] = gl[i]; }
        }
        if (tid < NN) ((float*)(smem + SM_BIAS))[tid] = g_bias[tid];
    }
    // --- Fill A tile: y = person0 + person1, split to bf16 hi/lo ---
    {
        const int m = tid >> 2;              // 64 rows, 4 threads/row
        const int k0 = (tid & 3) * 16;
        const int r = r0 + m;
        const int b = r >> 8, t = r & 255;
        const float* p0 = x + (((b * 2 + 0) * NT + t) * NV + v) * NC + k0;
        const float* p1 = p0 + (size_t)NT * NV * NC;
        char* Ah = smem + SM_AH + m * ROWB + k0 * 2;
        char* Al = smem + SM_AL + m * ROWB + k0 * 2;
        #pragma unroll
        for (int i = 0; i < 4; i++) {
            float4 a0 = *(const float4*)(p0 + i * 4);
            float4 a1 = *(const float4*)(p1 + i * 4);
            float y0 = a0.x + a1.x, y1 = a0.y + a1.y;
            float y2 = a0.z + a1.z, y3 = a0.w + a1.w;
            unsigned short h0,l0,h1,l1,h2,l2,h3,l3;
            split_bf16(y0, h0, l0); split_bf16(y1, h1, l1);
            split_bf16(y2, h2, l2); split_bf16(y3, h3, l3);
            uint2 ph, pl;
            ph.x = (uint32_t)h0 | ((uint32_t)h1 << 16);
            ph.y = (uint32_t)h2 | ((uint32_t)h3 << 16);
            pl.x = (uint32_t)l0 | ((uint32_t)l1 << 16);
            pl.y = (uint32_t)l2 | ((uint32_t)l3 << 16);
            *(uint2*)(Ah + i * 8) = ph;
            *(uint2*)(Al + i * 8) = pl;
        }
        if ((tid & 3) == 0) {                // zero K pad bytes 128..143
            *(uint4*)(smem + SM_AH + m * ROWB + 128) = make_uint4(0,0,0,0);
            *(uint4*)(smem + SM_AL + m * ROWB + 128) = make_uint4(0,0,0,0);
        }
    }
    __syncthreads();

    // --- Main MMA loop: warp tile 32m x 32n ---
    const int warp_m = (wid & 1) * 32;
    const int warp_n = (wid >> 1) * 32;

    const uint32_t a_lane = ((lane & 7) + ((lane >> 3) & 1) * 8) * ROWB
                          + ((lane >> 4) & 1) * 16;
    // B x4 lane map: mat0=(n0-7,k0-7), mat1=(n0-7,k8-15), mat2=(n8-15,k0-7), mat3=(n8-15,k8-15)
    const uint32_t b_lane = ((lane & 7) + ((lane >> 4) & 1) * 8) * ROWB
                          + ((lane >> 3) & 1) * 16;

    float acc[2][4][4];
    #pragma unroll
    for (int i = 0; i < 2; i++)
        #pragma unroll
        for (int j = 0; j < 4; j++)
            #pragma unroll
            for (int q = 0; q < 4; q++) acc[i][j][q] = 0.f;

    const uint32_t aBaseH = sbase + SM_AH + warp_m * ROWB + a_lane;
    const uint32_t aBaseL = sbase + SM_AL + warp_m * ROWB + a_lane;
    const uint32_t bBaseH = sbase + SM_BH + warp_n * ROWB + b_lane;
    const uint32_t bBaseL = sbase + SM_BL + warp_n * ROWB + b_lane;

    #pragma unroll
    for (int ks = 0; ks < 4; ks++) {
        uint32_t ah[2][4], al[2][4];
        #pragma unroll
        for (int mb = 0; mb < 2; mb++) {
            ldsm_x4(ah[mb], aBaseH + mb * 16 * ROWB + ks * 32);
            ldsm_x4(al[mb], aBaseL + mb * 16 * ROWB + ks * 32);
        }
        #pragma unroll
        for (int np = 0; np < 2; np++) {     // each x4 covers 16 n-rows
            uint32_t bh[4], bl[4];
            ldsm_x4(bh, bBaseH + np * 16 * ROWB + ks * 32);
            ldsm_x4(bl, bBaseL + np * 16 * ROWB + ks * 32);
            #pragma unroll
            for (int h = 0; h < 2; h++) {    // nb = np*2 + h
                #pragma unroll
                for (int mb = 0; mb < 2; mb++) {
                    mma_bf16(acc[mb][np * 2 + h], ah[mb], bh + h * 2);
                    mma_bf16(acc[mb][np * 2 + h], al[mb], bh + h * 2);
                    mma_bf16(acc[mb][np * 2 + h], ah[mb], bl + h * 2);
                }
            }
        }
    }

    // --- Epilogue: bias + ReLU + store ---
    const float* bs = (const float*)(smem + SM_BIAS);
    const int qrow = lane >> 2;
    const int qcol = (lane & 3) * 2;
    #pragma unroll
    for (int mb = 0; mb < 2; mb++) {
        #pragma unroll
        for (int nb = 0; nb < 4; nb++) {
            const int n = warp_n + nb * 8 + qcol;
            const float b0 = bs[n], b1 = bs[n + 1];
            const int mlo = warp_m + mb * 16 + qrow;
            float* o0 = out + ((size_t)(r0 + mlo) * NV + v) * NN + n;
            float* o1 = o0 + (size_t)8 * NV * NN;
            float2 r0v, r1v;
            r0v.x = fmaxf(acc[mb][nb][0] + b0, 0.f);
            r0v.y = fmaxf(acc[mb][nb][1] + b1, 0.f);
            r1v.x = fmaxf(acc[mb][nb][2] + b0, 0.f);
            r1v.y = fmaxf(acc[mb][nb][3] + b1, 0.f);
            *(float2*)o0 = r0v;
            *(float2*)o1 = r1v;
        }
    }
}

extern "C" void kernel_launch(void* const* d_in, const int* in_sizes, int n_in,
                              void* d_out, int out_size)
{
    const float* inputs = (const float*)d_in[0];
    const float* mat    = (const float*)d_in[1];
    const float* amask  = (const float*)d_in[2];
    const float* kern   = (const float*)d_in[3];
    const float* gamma  = (const float*)d_in[4];
    const float* beta   = (const float*)d_in[5];
    const float* mean   = (const float*)d_in[6];
    const float* var    = (const float*)d_in[7];
    float* out = (float*)d_out;

    cudaFuncSetAttribute(gemm_kernel,
                         cudaFuncAttributeMaxDynamicSharedMemorySize,
                         SMEM_BYTES);

    prep_kernel<<<dim3(NV, 4), NN>>>(mat, amask, kern, gamma, beta, mean, var);
    gemm_kernel<<<dim3((NB * NT) / TILE_M, NV), 256, SMEM_BYTES>>>(inputs, out);
}

// round 7
// speedup vs baseline: 1.8114x; 1.1574x over previous
#include <cuda_runtime.h>
#include <cuda_bf16.h>
#include <cstdint>

#define NV 17
#define NC 64
#define NN 128
#define NB 64
#define NT 256
#define TILE_M 64

#define KPAD 72                       // A rows: 64 bf16 + 8 pad -> 144B, LDSM conflict-free
#define ROWB (KPAD * 2)

// smem byte offsets (A tiles + bias only; B never touches smem)
#define SM_AH 0
#define SM_AL (SM_AH + TILE_M * ROWB)       // 9216
#define SM_BIAS (SM_AL + TILE_M * ROWB)     // 18432
#define SMEM_BYTES (SM_BIAS + NN * 4)       // 18944

// B in fragment-direct layout: [v][n_blk(16)][ks(4)][lane(32)] of uint4{b0h,b1h,b0l,b1l}
__device__ __align__(16) uint4 g_Wfrag[NV * 16 * 4 * 32];
__device__ __align__(16) float g_bias[NN];

__device__ __forceinline__ uint32_t smem_u32(const void* p) {
    uint32_t a;
    asm("{ .reg .u64 t; cvta.to.shared.u64 t, %1; cvt.u32.u64 %0, t; }" : "=r"(a) : "l"(p));
    return a;
}

__device__ __forceinline__ void split_bf16(float x, unsigned short& h, unsigned short& l) {
    __nv_bfloat16 hb = __float2bfloat16(x);
    h = *(unsigned short*)&hb;
    float r = x - __bfloat162float(hb);
    __nv_bfloat16 lb = __float2bfloat16(r);
    l = *(unsigned short*)&lb;
}

__device__ __forceinline__ void ldsm_x4(uint32_t* r, uint32_t addr) {
    asm volatile("ldmatrix.sync.aligned.m8n8.x4.shared.b16 {%0,%1,%2,%3}, [%4];"
        : "=r"(r[0]), "=r"(r[1]), "=r"(r[2]), "=r"(r[3]) : "r"(addr));
}
__device__ __forceinline__ void mma_bf16(float* c, const uint32_t* a, const uint32_t* b) {
    asm volatile(
        "mma.sync.aligned.m16n8k16.row.col.f32.bf16.bf16.f32 "
        "{%0,%1,%2,%3}, {%4,%5,%6,%7}, {%8,%9}, {%0,%1,%2,%3};"
        : "+f"(c[0]), "+f"(c[1]), "+f"(c[2]), "+f"(c[3])
        : "r"(a[0]), "r"(a[1]), "r"(a[2]), "r"(a[3]), "r"(b[0]), "r"(b[1]));
}

__device__ __forceinline__ uint32_t packhl(unsigned short a, unsigned short b) {
    return (uint32_t)a | ((uint32_t)b << 16);
}

// ---------------------------------------------------------------------------
// Prep: grid NV, 128 thr. Warp-parallel softmax (no serial block reductions),
// then emit W'[v] in mma-fragment layout, BN folded.
// ---------------------------------------------------------------------------
__global__ void prep_kernel(const float* __restrict__ mat,
                            const float* __restrict__ amask,
                            const float* __restrict__ kern,
                            const float* __restrict__ gamma,
                            const float* __restrict__ beta,
                            const float* __restrict__ mean,
                            const float* __restrict__ var)
{
    const int v = blockIdx.x;
    const int tid = threadIdx.x;          // 0..127
    const int lane = tid & 31, w = tid >> 5;
    __shared__ float aacc[4][NN];

    #pragma unroll
    for (int q = 0; q < 4; q++) aacc[q][tid] = 0.f;
    __syncthreads();

    // warp w handles m = w, w+4, w+8, w+12, w+16
    #pragma unroll
    for (int r = 0; r < 5; r++) {
        const int m = w + r * 4;
        if (m < NV) {
            const float mt = __ldg(&mat[m * NV + v]);
            float z[4];
            #pragma unroll
            for (int j = 0; j < 4; j++)
                z[j] = mt * __ldg(&amask[(m * NV + v) * NN + lane + j * 32]);
            float mx = fmaxf(fmaxf(z[0], z[1]), fmaxf(z[2], z[3]));
            #pragma unroll
            for (int o = 16; o > 0; o >>= 1)
                mx = fmaxf(mx, __shfl_xor_sync(0xffffffffu, mx, o));
            float e[4]; float s = 0.f;
            #pragma unroll
            for (int j = 0; j < 4; j++) { e[j] = expf(z[j] - mx); s += e[j]; }
            #pragma unroll
            for (int o = 16; o > 0; o >>= 1)
                s += __shfl_xor_sync(0xffffffffu, s, o);
            const float inv = 1.f / s;
            #pragma unroll
            for (int j = 0; j < 4; j++)
                aacc[w][lane + j * 32] += e[j] * inv;
        }
    }
    __syncthreads();

    const int n = tid;
    const float scale = gamma[n] * rsqrtf(var[n] + 1e-3f);
    const float an = (aacc[0][n] + aacc[1][n] + aacc[2][n] + aacc[3][n]) * scale;

    // emit fragments: lane l of n_blk holds rows n = n_blk*8 + l>>2,
    // k-pairs (l&3)*2 (+1), b1 at k+8; ks selects 16-wide k chunk.
    uint4* dst = g_Wfrag + ((size_t)v * 16 + (n >> 3)) * 4 * 32 + (n & 7) * 4;
    #pragma unroll
    for (int ks = 0; ks < 4; ks++) {
        float wv[16];
        #pragma unroll
        for (int i = 0; i < 16; i++)
            wv[i] = __ldg(&kern[(v * NC + ks * 16 + i) * NN + n]) * an;
        unsigned short h[16], l[16];
        #pragma unroll
        for (int i = 0; i < 16; i++) split_bf16(wv[i], h[i], l[i]);
        #pragma unroll
        for (int q = 0; q < 4; q++) {
            uint4 u;
            u.x = packhl(h[q*2],     h[q*2+1]);      // b0 hi (k, k+1)
            u.y = packhl(h[q*2+8],   h[q*2+9]);      // b1 hi (k+8, k+9)
            u.z = packhl(l[q*2],     l[q*2+1]);      // b0 lo
            u.w = packhl(l[q*2+8],   l[q*2+9]);      // b1 lo
            dst[ks * 32 + q] = u;
        }
    }
    if (v == 0) g_bias[n] = beta[n] - mean[n] * scale;
}

// ---------------------------------------------------------------------------
// GEMM: CTA 64m x 128n for one v, K=64. 8 warps (2m x 4n), warp tile 32x32.
// A through smem+ldmatrix (hi/lo), B fragments LDG'd straight from L2.
// ---------------------------------------------------------------------------
__global__ void __launch_bounds__(256, 3)
gemm_kernel(const float* __restrict__ x, float* __restrict__ out)
{
    extern __shared__ __align__(16) char smem[];
    const uint32_t sbase = smem_u32(smem);
    const int tid = threadIdx.x;
    const int wid = tid >> 5;
    const int lane = tid & 31;
    const int v = blockIdx.y;
    const int r0 = blockIdx.x * TILE_M;

    // --- Fill A tile: y = person0 + person1, split to bf16 hi/lo ---
    {
        const int m = tid >> 2;              // 64 rows, 4 threads/row
        const int k0 = (tid & 3) * 16;
        const int r = r0 + m;
        const int b = r >> 8, t = r & 255;
        const float* p0 = x + (((b * 2 + 0) * NT + t) * NV + v) * NC + k0;
        const float* p1 = p0 + (size_t)NT * NV * NC;
        char* Ah = smem + SM_AH + m * ROWB + k0 * 2;
        char* Al = smem + SM_AL + m * ROWB + k0 * 2;
        #pragma unroll
        for (int i = 0; i < 4; i++) {
            float4 a0 = *(const float4*)(p0 + i * 4);
            float4 a1 = *(const float4*)(p1 + i * 4);
            float y0 = a0.x + a1.x, y1 = a0.y + a1.y;
            float y2 = a0.z + a1.z, y3 = a0.w + a1.w;
            unsigned short h0,l0,h1,l1,h2,l2,h3,l3;
            split_bf16(y0, h0, l0); split_bf16(y1, h1, l1);
            split_bf16(y2, h2, l2); split_bf16(y3, h3, l3);
            uint2 ph, pl;
            ph.x = packhl(h0, h1); ph.y = packhl(h2, h3);
            pl.x = packhl(l0, l1); pl.y = packhl(l2, l3);
            *(uint2*)(Ah + i * 8) = ph;
            *(uint2*)(Al + i * 8) = pl;
        }
        if ((tid & 3) == 0) {                // zero K pad bytes 128..143
            *(uint4*)(smem + SM_AH + m * ROWB + 128) = make_uint4(0,0,0,0);
            *(uint4*)(smem + SM_AL + m * ROWB + 128) = make_uint4(0,0,0,0);
        }
        if (tid < NN) ((float*)(smem + SM_BIAS))[tid] = g_bias[tid];
    }
    __syncthreads();

    const int warp_m = (wid & 1) * 32;
    const int warp_n = (wid >> 1) * 32;

    const uint32_t a_lane = ((lane & 7) + ((lane >> 3) & 1) * 8) * ROWB
                          + ((lane >> 4) & 1) * 16;

    float acc[2][4][4];
    #pragma unroll
    for (int i = 0; i < 2; i++)
        #pragma unroll
        for (int j = 0; j < 4; j++)
            #pragma unroll
            for (int q = 0; q < 4; q++) acc[i][j][q] = 0.f;

    const uint32_t aBaseH = sbase + SM_AH + warp_m * ROWB + a_lane;
    const uint32_t aBaseL = sbase + SM_AL + warp_m * ROWB + a_lane;
    // B fragment base for this warp: n_blks (wid>>1)*4 .. +3
    const uint4* Bf = g_Wfrag + (((size_t)v * 16 + (wid >> 1) * 4) * 4) * 32 + lane;

    #pragma unroll
    for (int ks = 0; ks < 4; ks++) {
        uint32_t ah[2][4], al[2][4];
        #pragma unroll
        for (int mb = 0; mb < 2; mb++) {
            ldsm_x4(ah[mb], aBaseH + mb * 16 * ROWB + ks * 32);
            ldsm_x4(al[mb], aBaseL + mb * 16 * ROWB + ks * 32);
        }
        #pragma unroll
        for (int nb = 0; nb < 4; nb++) {
            uint4 bu = __ldg(Bf + (nb * 4 + ks) * 32);
            const uint32_t* bh = &bu.x;       // {b0h, b1h}
            const uint32_t* bl = &bu.z;       // {b0l, b1l}
            #pragma unroll
            for (int mb = 0; mb < 2; mb++) {
                mma_bf16(acc[mb][nb], ah[mb], bh);
                mma_bf16(acc[mb][nb], al[mb], bh);
                mma_bf16(acc[mb][nb], ah[mb], bl);
            }
        }
    }

    // --- Epilogue: bias + ReLU + store ---
    const float* bs = (const float*)(smem + SM_BIAS);
    const int qrow = lane >> 2;
    const int qcol = (lane & 3) * 2;
    #pragma unroll
    for (int mb = 0; mb < 2; mb++) {
        #pragma unroll
        for (int nb = 0; nb < 4; nb++) {
            const int n = warp_n + nb * 8 + qcol;
            const float b0 = bs[n], b1 = bs[n + 1];
            const int mlo = warp_m + mb * 16 + qrow;
            float* o0 = out + ((size_t)(r0 + mlo) * NV + v) * NN + n;
            float* o1 = o0 + (size_t)8 * NV * NN;
            float2 r0v, r1v;
            r0v.x = fmaxf(acc[mb][nb][0] + b0, 0.f);
            r0v.y = fmaxf(acc[mb][nb][1] + b1, 0.f);
            r1v.x = fmaxf(acc[mb][nb][2] + b0, 0.f);
            r1v.y = fmaxf(acc[mb][nb][3] + b1, 0.f);
            *(float2*)o0 = r0v;
            *(float2*)o1 = r1v;
        }
    }
}

extern "C" void kernel_launch(void* const* d_in, const int* in_sizes, int n_in,
                              void* d_out, int out_size)
{
    const float* inputs = (const float*)d_in[0];
    const float* mat    = (const float*)d_in[1];
    const float* amask  = (const float*)d_in[2];
    const float* kern   = (const float*)d_in[3];
    const float* gamma  = (const float*)d_in[4];
    const float* beta   = (const float*)d_in[5];
    const float* mean   = (const float*)d_in[6];
    const float* var    = (const float*)d_in[7];
    float* out = (float*)d_out;

    cudaFuncSetAttribute(gemm_kernel,
                         cudaFuncAttributeMaxDynamicSharedMemorySize,
                         SMEM_BYTES);

    prep_kernel<<<NV, NN>>>(mat, amask, kern, gamma, beta, mean, var);
    gemm_kernel<<<dim3((NB * NT) / TILE_M, NV), 256, SMEM_BYTES>>>(inputs, out);
}